// round 11
// baseline (speedup 1.0000x reference)
#include <cuda_runtime.h>
#include <cuda_bf16.h>
#include <cstddef>

// ---------------------------------------------------------------------------
// RSFM = 2x conv1x1 in  ->  6x fused (rmsnorm + mamba-style block + residual)
//        -> conv1x1 out.   h-update is ELEMENT-WISE over L (no scan).
// R8: warp-owned positions for the whole x_proj->out_proj tail (zero CTA
//     barriers after the conv stage), h scratch transposed to [pos][s][d]
//     for coalesced per-s warp accesses, A staged transposed [16][128],
//     2-pos stage-B blocking, 864 threads (27 warps = 27 positions).
// ---------------------------------------------------------------------------

#define LSEQ   4096
#define DM     64
#define DI     128
#define DS     16
#define TT     27
#define TPB_   152                   // tiles per batch: 151*27 + 19
#define NTILES (2 * TPB_)            // 304
#define NTHR   864                   // 27 warps
#define CONV_OUT_ELEMS (2 * 64 * LSEQ)

// shared memory layout (float offsets)
#define OFF_WIN 0        // in_proj^T  [k=64][o=256]
#define OFF_WX  16384    // x_proj^T   [d=128][o=64]
#define OFF_WDT 24576    // dt_proj^T  [r=32][d=128]
#define OFF_WO  28672    // out_proj^T [d=128][c=64]
#define OFF_AT  36864    // A transposed [s=16][d=128] = -exp(A_log)
#define OFF_CW  38912    // conv1d w [t=3][d=128]
#define OFF_CB  39296
#define OFF_DTB 39424
#define OFF_DP  39552
#define OFF_NW  39680
#define OFF_XN  39744    // rmsnormed input [29][64]
#define OFF_XCR 41600    // raw xc (pre-conv) [29][128]
#define OFF_SZ  45312    // silu(z) [27][128]
#define OFF_XC  48768    // conv+silu xc; tail overwrites row t with gated y
#define SMEM_FLOATS 52224
#define SMEM_BYTES  (SMEM_FLOATS * 4)   // 208896 B

// persistent scratch (device globals)
__device__ float g_rgb [2 * LSEQ * DM];
__device__ float g_dte [2 * LSEQ * DM];
__device__ float g_bufA[2 * LSEQ * DM];
__device__ float g_bufB[2 * LSEQ * DM];
__device__ float g_h   [(size_t)2 * LSEQ * DI * DS];   // [b][l][s][d] layout!

__device__ __forceinline__ float sigmoidf_(float x) { return 1.f / (1.f + __expf(-x)); }
__device__ __forceinline__ float softplusf_(float x) {
    return (x > 15.f) ? x : __logf(1.f + __expf(x));
}

// ---------------------------------------------------------------------------
// input conv1x1
// ---------------------------------------------------------------------------
__global__ __launch_bounds__(256) void conv_in_kernel(
    const float* __restrict__ x, const float* __restrict__ w,
    const float* __restrict__ bias, int which)
{
    __shared__ float xs[64 * 64];
    __shared__ float wt[64 * 64];
    __shared__ float bs[64];
    float* out = which ? g_dte : g_rgb;

    const int tile = blockIdx.x;
    const int b  = tile >> 6;
    const int l0 = (tile & 63) << 6;
    const int tid = threadIdx.x;

    for (int i = tid; i < 4096; i += 256) { int o = i >> 6, c = i & 63; wt[c * 64 + o] = w[i]; }
    if (tid < 64) bs[tid] = bias[tid];
    for (int i = tid; i < 4096; i += 256) {
        int c = i >> 6, p = i & 63;
        xs[i] = x[((size_t)b * 64 + c) * LSEQ + l0 + p];
    }
    __syncthreads();

    const int pg = tid >> 6;
    const int o  = tid & 63;
    for (int p = pg; p < 64; p += 4) {
        float acc = bs[o];
        #pragma unroll 8
        for (int c = 0; c < 64; c++) acc = fmaf(xs[c * 64 + p], wt[c * 64 + o], acc);
        out[((size_t)b * LSEQ + l0 + p) * DM + o] = acc;
    }
}

// ---------------------------------------------------------------------------
// final conv1x1 (NCHW out)
// ---------------------------------------------------------------------------
__global__ __launch_bounds__(256) void conv_out_kernel(
    const float* __restrict__ w, const float* __restrict__ bias, float* __restrict__ out)
{
    __shared__ float xs[64 * 65];
    __shared__ float ws[64 * 64];
    __shared__ float bs[64];

    const int tile = blockIdx.x;
    const int b  = tile >> 6;
    const int l0 = (tile & 63) << 6;
    const int tid = threadIdx.x;

    for (int i = tid; i < 4096; i += 256) ws[i] = w[i];
    if (tid < 64) bs[tid] = bias[tid];
    for (int i = tid; i < 4096; i += 256) {
        int p = i >> 6, c = i & 63;
        xs[p * 65 + c] = g_bufB[((size_t)b * LSEQ + l0 + p) * DM + c];
    }
    __syncthreads();

    const int wid = tid >> 5, lane = tid & 31;
    for (int o = wid; o < 64; o += 8)
        for (int p = lane; p < 64; p += 32) {
            float acc = bs[o];
            #pragma unroll 8
            for (int c = 0; c < 64; c++) acc = fmaf(xs[p * 65 + c], ws[o * 64 + c], acc);
            out[((size_t)b * 64 + o) * LSEQ + l0 + p] = acc;
        }
}

// ---------------------------------------------------------------------------
// One fused residual block.  864 threads = 27 warps; warp w owns position w
// for the entire x_proj -> out_proj tail (no CTA barriers after conv).
// ---------------------------------------------------------------------------
__global__ __launch_bounds__(NTHR, 1) void rsfm_block_kernel(
    int kblk,
    const float* __restrict__ inpw, const float* __restrict__ cvw, const float* __restrict__ cvb,
    const float* __restrict__ xpw,  const float* __restrict__ dtw, const float* __restrict__ dtb,
    const float* __restrict__ alog, const float* __restrict__ dpw, const float* __restrict__ opw,
    const float* __restrict__ normw, float* __restrict__ h_final)
{
    extern __shared__ float sm[];
    const int tid  = threadIdx.x;
    const int wid  = tid >> 5, lane = tid & 31;

    const float* base  = (kblk & 1) ? g_dte : g_rgb;
    const float* prevp = (kblk == 0) ? (const float*)0 : ((kblk & 1) ? g_bufA : g_bufB);
    float*       outb  = (kblk & 1) ? g_bufB : g_bufA;
    const bool   rd_h  = (kblk != 0);
    const bool   last  = (kblk == 5);

    const int tile = blockIdx.x;
    const int b    = tile / TPB_;
    const int l0   = (tile - b * TPB_) * TT;
    const int cnt  = (TT < LSEQ - l0) ? TT : (LSEQ - l0);     // 27 or 19
    const int ne   = cnt + 2;

    // L2 prefetch of this tile's h (contiguous [pos][s][d] rows)
    if (rd_h) {
        const float* hb = g_h + (size_t)(b * LSEQ + l0) * (DI * DS);
        for (int idx = tid; idx < cnt * 64; idx += NTHR)
            asm volatile("prefetch.global.L2 [%0];" :: "l"(hb + idx * 32));
    }

    // ---- stage weights into smem ----
    for (int i = tid; i < 256 * 64; i += NTHR) { int o = i >> 6, k = i & 63;  sm[OFF_WIN + k * 256 + o] = inpw[i]; }
    for (int i = tid; i < 64 * 128; i += NTHR) { int o = i >> 7, d = i & 127; sm[OFF_WX  + d * 64  + o] = xpw[i]; }
    for (int i = tid; i < 128 * 32; i += NTHR) { int r = i >> 7, d = i & 127; sm[OFF_WDT + i] = dtw[d * 32 + r]; }
    for (int i = tid; i < 64 * 128; i += NTHR) { int c = i >> 7, d = i & 127; sm[OFF_WO  + d * 64  + c] = opw[i]; }
    for (int i = tid; i < 16 * 128; i += NTHR) { int s = i >> 7, d = i & 127; sm[OFF_AT + i] = -__expf(alog[d * 16 + s]); }
    if (tid < 384) { int d = tid / 3, t = tid % 3; sm[OFF_CW + t * 128 + d] = cvw[tid]; }
    if (tid >= 384 && tid < 512) { int j = tid - 384; sm[OFF_CB + j] = cvb[j]; sm[OFF_DTB + j] = dtb[j]; sm[OFF_DP + j] = dpw[j]; }
    if (tid < 64)  sm[OFF_NW + tid] = normw[tid];
    __syncthreads();

    // ---- Stage A: (base + prev) -> rmsnorm -> XN[ne][64] ----
    for (int t = wid; t < ne; t += 27) {
        int l = l0 - 1 + t;
        float x0 = 0.f, x1 = 0.f;
        if (l >= 0 && l < LSEQ) {
            size_t off = ((size_t)b * LSEQ + l) * DM;
            x0 = base[off + lane]; x1 = base[off + lane + 32];
            if (prevp) { x0 += prevp[off + lane]; x1 += prevp[off + lane + 32]; }
        }
        float ss = x0 * x0 + x1 * x1;
        #pragma unroll
        for (int o = 16; o; o >>= 1) ss += __shfl_xor_sync(0xffffffffu, ss, o);
        float inv = rsqrtf(ss * (1.f / 64.f) + 1e-5f);
        sm[OFF_XN + t * 64 + lane]      = x0 * inv * sm[OFF_NW + lane];
        sm[OFF_XN + t * 64 + lane + 32] = x1 * inv * sm[OFF_NW + lane + 32];
    }
    __syncthreads();

    // ---- Stage B: in_proj 64->256, 2 pos x 4 out per thread ----
    {
        const int npg = (ne + 1) >> 1;        // 15 (or 11)
        for (int idx = tid; idx < (npg << 6); idx += NTHR) {
            const int pg = idx >> 6;
            const int og = (idx & 63) << 2;
            const int t0 = pg << 1;
            const int pmax = ne - t0;          // >= 1
            float4 a0 = make_float4(0.f, 0.f, 0.f, 0.f);
            float4 a1 = make_float4(0.f, 0.f, 0.f, 0.f);
            const float* wb = &sm[OFF_WIN + og];
            const float* xb = &sm[OFF_XN + (t0 << 6)];
            #pragma unroll 4
            for (int k = 0; k < 64; k += 4) {
                float4 w0 = *(const float4*)(wb + (k    ) * 256);
                float4 w1 = *(const float4*)(wb + (k + 1) * 256);
                float4 w2 = *(const float4*)(wb + (k + 2) * 256);
                float4 w3 = *(const float4*)(wb + (k + 3) * 256);
                float4 xa = *(const float4*)(xb + k);
                float4 xc2 = *(const float4*)(xb + 64 + k);   // speculative (in-bounds region)
                a0.x = fmaf(xa.x, w0.x, a0.x); a0.y = fmaf(xa.x, w0.y, a0.y); a0.z = fmaf(xa.x, w0.z, a0.z); a0.w = fmaf(xa.x, w0.w, a0.w);
                a0.x = fmaf(xa.y, w1.x, a0.x); a0.y = fmaf(xa.y, w1.y, a0.y); a0.z = fmaf(xa.y, w1.z, a0.z); a0.w = fmaf(xa.y, w1.w, a0.w);
                a0.x = fmaf(xa.z, w2.x, a0.x); a0.y = fmaf(xa.z, w2.y, a0.y); a0.z = fmaf(xa.z, w2.z, a0.z); a0.w = fmaf(xa.z, w2.w, a0.w);
                a0.x = fmaf(xa.w, w3.x, a0.x); a0.y = fmaf(xa.w, w3.y, a0.y); a0.z = fmaf(xa.w, w3.z, a0.z); a0.w = fmaf(xa.w, w3.w, a0.w);
                a1.x = fmaf(xc2.x, w0.x, a1.x); a1.y = fmaf(xc2.x, w0.y, a1.y); a1.z = fmaf(xc2.x, w0.z, a1.z); a1.w = fmaf(xc2.x, w0.w, a1.w);
                a1.x = fmaf(xc2.y, w1.x, a1.x); a1.y = fmaf(xc2.y, w1.y, a1.y); a1.z = fmaf(xc2.y, w1.z, a1.z); a1.w = fmaf(xc2.y, w1.w, a1.w);
                a1.x = fmaf(xc2.z, w2.x, a1.x); a1.y = fmaf(xc2.z, w2.y, a1.y); a1.z = fmaf(xc2.z, w2.z, a1.z); a1.w = fmaf(xc2.z, w2.w, a1.w);
                a1.x = fmaf(xc2.w, w3.x, a1.x); a1.y = fmaf(xc2.w, w3.y, a1.y); a1.z = fmaf(xc2.w, w3.z, a1.z); a1.w = fmaf(xc2.w, w3.w, a1.w);
            }
            #pragma unroll
            for (int p = 0; p < 2; p++) {
                const int t = t0 + p;
                float4 av = p ? a1 : a0;
                if (p < pmax) {
                    if (og < 128) {
                        *(float4*)&sm[OFF_XCR + t * 128 + og] = av;
                    } else if (t >= 1 && t <= cnt) {
                        const int zi = (t - 1) * 128 + og - 128;
                        sm[OFF_SZ + zi + 0] = av.x * sigmoidf_(av.x);
                        sm[OFF_SZ + zi + 1] = av.y * sigmoidf_(av.y);
                        sm[OFF_SZ + zi + 2] = av.z * sigmoidf_(av.z);
                        sm[OFF_SZ + zi + 3] = av.w * sigmoidf_(av.w);
                    }
                }
            }
        }
    }
    __syncthreads();

    // ---- Stage C: depthwise conv1d (k=3, pad 1) + silu -> XC[cnt][128] ----
    for (int idx = tid; idx < cnt * 128; idx += NTHR) {
        int ti = idx >> 7, d = idx & 127;
        float v = sm[OFF_CB + d];
        v = fmaf(sm[OFF_CW +       d], sm[OFF_XCR +  ti      * 128 + d], v);
        v = fmaf(sm[OFF_CW + 128 + d], sm[OFF_XCR + (ti + 1) * 128 + d], v);
        v = fmaf(sm[OFF_CW + 256 + d], sm[OFF_XCR + (ti + 2) * 128 + d], v);
        sm[OFF_XC + idx] = v * sigmoidf_(v);
    }
    __syncthreads();

    // ======================= warp-owned tail: position t = wid ==============
    if (wid < cnt) {
        const int t = wid;
        const float* XCrow = &sm[OFF_XC + t * 128];

        // ---- D: x_proj 128->64, 2 outputs per lane (o = 2*lane, 2*lane+1) ----
        float d0 = 0.f, d1 = 0.f;
        {
            const float* wb = &sm[OFF_WX + 2 * lane];
            #pragma unroll 8
            for (int d4 = 0; d4 < 32; d4++) {
                float4 xv = *(const float4*)(XCrow + 4 * d4);     // broadcast
                float2 w0 = *(const float2*)(wb + (4 * d4    ) * 64);
                float2 w1 = *(const float2*)(wb + (4 * d4 + 1) * 64);
                float2 w2 = *(const float2*)(wb + (4 * d4 + 2) * 64);
                float2 w3 = *(const float2*)(wb + (4 * d4 + 3) * 64);
                d0 = fmaf(xv.x, w0.x, d0); d1 = fmaf(xv.x, w0.y, d1);
                d0 = fmaf(xv.y, w1.x, d0); d1 = fmaf(xv.y, w1.y, d1);
                d0 = fmaf(xv.z, w2.x, d0); d1 = fmaf(xv.z, w2.y, d1);
                d0 = fmaf(xv.w, w3.x, d0); d1 = fmaf(xv.w, w3.y, d1);
            }
        }
        // lane l holds dbc[2l] (d0), dbc[2l+1] (d1).
        // delta_in = dbc[0:32] (lanes 0-15), B = dbc[32:48], C = dbc[48:64].

        // ---- E: dt_proj 32->128 + bias + softplus, 4 outputs (d = 4*lane+j) ----
        float4 dl;
        {
            float4 acc = *(const float4*)&sm[OFF_DTB + 4 * lane];
            const float* wb = &sm[OFF_WDT + 4 * lane];
            #pragma unroll
            for (int r = 0; r < 32; r++) {
                float din = __shfl_sync(0xffffffffu, (r & 1) ? d1 : d0, r >> 1);
                float4 wv = *(const float4*)(wb + r * 128);
                acc.x = fmaf(din, wv.x, acc.x); acc.y = fmaf(din, wv.y, acc.y);
                acc.z = fmaf(din, wv.z, acc.z); acc.w = fmaf(din, wv.w, acc.w);
            }
            dl.x = softplusf_(acc.x); dl.y = softplusf_(acc.y);
            dl.z = softplusf_(acc.z); dl.w = softplusf_(acc.w);
        }

        // ---- F: SSM h-update + y (s-outer, coalesced h rows [pos][s][d]) ----
        float4 xc = *(const float4*)(XCrow + 4 * lane);
        float4 dx = make_float4(dl.x * xc.x, dl.y * xc.y, dl.z * xc.z, dl.w * xc.w);
        float4 y  = make_float4(0.f, 0.f, 0.f, 0.f);
        {
            const size_t hrow = (size_t)(b * LSEQ + l0 + t) * (DI * DS);
            #pragma unroll
            for (int s = 0; s < 16; s++) {
                float Bv = __shfl_sync(0xffffffffu, (s & 1) ? d1 : d0, 16 + (s >> 1));
                float Cv = __shfl_sync(0xffffffffu, (s & 1) ? d1 : d0, 24 + (s >> 1));
                float4 Av = *(const float4*)&sm[OFF_AT + s * 128 + 4 * lane];
                float4 ho = make_float4(0.f, 0.f, 0.f, 0.f);
                if (rd_h) ho = *(const float4*)(g_h + hrow + s * DI + 4 * lane);
                float4 hn;
                hn.x = fmaf(__expf(dl.x * Av.x), ho.x, dx.x * Bv);
                hn.y = fmaf(__expf(dl.y * Av.y), ho.y, dx.y * Bv);
                hn.z = fmaf(__expf(dl.z * Av.z), ho.z, dx.z * Bv);
                hn.w = fmaf(__expf(dl.w * Av.w), ho.w, dx.w * Bv);
                y.x = fmaf(hn.x, Cv, y.x); y.y = fmaf(hn.y, Cv, y.y);
                y.z = fmaf(hn.z, Cv, y.z); y.w = fmaf(hn.w, Cv, y.w);
                if (last) {
                    size_t fb = ((size_t)(b * LSEQ + l0 + t) * DI + 4 * lane) * DS + s;
                    h_final[fb]          = hn.x;
                    h_final[fb + DS]     = hn.y;
                    h_final[fb + 2 * DS] = hn.z;
                    h_final[fb + 3 * DS] = hn.w;
                } else {
                    *(float4*)(g_h + hrow + s * DI + 4 * lane) = hn;
                }
            }
        }
        // y += Dp*xc ; gate with silu(z)
        {
            float4 dp = *(const float4*)&sm[OFF_DP + 4 * lane];
            float4 szv = *(const float4*)&sm[OFF_SZ + t * 128 + 4 * lane];
            y.x = fmaf(dp.x, xc.x, y.x) * szv.x;
            y.y = fmaf(dp.y, xc.y, y.y) * szv.y;
            y.z = fmaf(dp.z, xc.z, y.z) * szv.z;
            y.w = fmaf(dp.w, xc.w, y.w) * szv.w;
        }
        // stash gated y into this warp's XC row (warp-private)
        *(float4*)&sm[OFF_XC + t * 128 + 4 * lane] = y;
        __syncwarp();

        // ---- G: out_proj 128->64 + residual, 2 outputs per lane ----
        {
            float2 acc = *(const float2*)&sm[OFF_XN + (t + 1) * 64 + 2 * lane];
            const float* wb = &sm[OFF_WO + 2 * lane];
            #pragma unroll 8
            for (int d4 = 0; d4 < 32; d4++) {
                float4 gv = *(const float4*)&sm[OFF_XC + t * 128 + 4 * d4];  // broadcast
                float2 w0 = *(const float2*)(wb + (4 * d4    ) * 64);
                float2 w1 = *(const float2*)(wb + (4 * d4 + 1) * 64);
                float2 w2 = *(const float2*)(wb + (4 * d4 + 2) * 64);
                float2 w3 = *(const float2*)(wb + (4 * d4 + 3) * 64);
                acc.x = fmaf(gv.x, w0.x, acc.x); acc.y = fmaf(gv.x, w0.y, acc.y);
                acc.x = fmaf(gv.y, w1.x, acc.x); acc.y = fmaf(gv.y, w1.y, acc.y);
                acc.x = fmaf(gv.z, w2.x, acc.x); acc.y = fmaf(gv.z, w2.y, acc.y);
                acc.x = fmaf(gv.w, w3.x, acc.x); acc.y = fmaf(gv.w, w3.y, acc.y);
            }
            *(float2*)&outb[(size_t)(b * LSEQ + l0 + t) * DM + 2 * lane] = acc;
        }
    }
}

extern "C" void kernel_launch(void* const* d_in, const int* in_sizes, int n_in,
                              void* d_out, int out_size) {
    const float* rgb     = (const float*)d_in[0];
    const float* dte     = (const float*)d_in[1];
    const float* conv1_w = (const float*)d_in[2];
    const float* conv1_b = (const float*)d_in[3];
    const float* conv2_w = (const float*)d_in[4];
    const float* conv2_b = (const float*)d_in[5];
    const float* conv3_w = (const float*)d_in[6];
    const float* conv3_b = (const float*)d_in[7];
    const float* norm_w  = (const float*)d_in[8];
    const float* in_proj = (const float*)d_in[9];
    const float* cv_w    = (const float*)d_in[10];
    const float* cv_b    = (const float*)d_in[11];
    const float* xp_w    = (const float*)d_in[12];
    const float* dt_w    = (const float*)d_in[13];
    const float* dt_b    = (const float*)d_in[14];
    const float* A_log   = (const float*)d_in[15];
    const float* Dp      = (const float*)d_in[16];
    const float* op_w    = (const float*)d_in[17];
    float* out = (float*)d_out;
    float* h_final = out + CONV_OUT_ELEMS;

    cudaFuncSetAttribute(rsfm_block_kernel,
                         cudaFuncAttributeMaxDynamicSharedMemorySize, SMEM_BYTES);

    conv_in_kernel<<<128, 256>>>(rgb, conv1_w, conv1_b, 0);
    conv_in_kernel<<<128, 256>>>(dte, conv2_w, conv2_b, 1);

    for (int k = 0; k < 6; k++) {
        rsfm_block_kernel<<<NTILES, NTHR, SMEM_BYTES>>>(
            k, in_proj, cv_w, cv_b, xp_w, dt_w, dt_b, A_log, Dp, op_w, norm_w, h_final);
    }

    conv_out_kernel<<<128, 256>>>(conv3_w, conv3_b, out);
}